// round 1
// baseline (speedup 1.0000x reference)
#include <cuda_runtime.h>
#include <math_constants.h>
#include <cstdint>

// VectorQuantizer: latents [64,32,32,64] f32, embedding [512,64] f32
// out[0] = vq_loss, out[1..] = quantized_st (numerically = gathered embedding
// re-rounded through l + (q - l)).

#define NROWS 65536
#define KEMB 512
#define DDIM 64
#define ROWS_PER_CTA 128
#define CANDS_PER_CHUNK 128
#define NCHUNKS (KEMB / CANDS_PER_CHUNK)
#define NTHREADS 256
#define NCTAS (NROWS / ROWS_PER_CTA)   // 512
#define XS_STRIDE 132                  // padded row stride (floats), 16B-aligned

__device__ float  g_bs[KEMB];     // ||e_k||^2, fp32 sequential (matches ref rounding scale)
__device__ double g_part[NCTAS];  // per-CTA loss partial sums

// ---------------- kernel 0: per-code squared norms ----------------
__global__ void vq_bs_kernel(const float* __restrict__ emb) {
    int k = blockIdx.x * blockDim.x + threadIdx.x;
    if (k < KEMB) {
        const float* e = emb + k * DDIM;
        float s = 0.f;
        #pragma unroll
        for (int d = 0; d < DDIM; d++)
            s = __fadd_rn(s, __fmul_rn(e[d], e[d]));
        g_bs[k] = s;
    }
}

// ---------------- kernel 1: distances + argmin + gather + ST + loss ----------------
__global__ __launch_bounds__(NTHREADS, 2)
void vq_main_kernel(const float* __restrict__ lat,
                    const float* __restrict__ emb,
                    float* __restrict__ quant /* = d_out + 1 */)
{
    extern __shared__ float sm[];
    float* Xs = sm;                       // [DDIM][XS_STRIDE] transposed latents tile
    float* Es = sm + DDIM * XS_STRIDE;    // [DDIM][XS_STRIDE] transposed code chunk
    float* As = Es + DDIM * XS_STRIDE;    // [ROWS_PER_CTA] ||x||^2

    const int tid = threadIdx.x;
    const int tx = tid & 15;              // candidate group 0..15
    const int ty = tid >> 4;              // row group 0..15
    const int rowBase = blockIdx.x * ROWS_PER_CTA;

    // ---- load X tile (32KB contiguous) transposed into smem ----
    {
        const float4* X4 = (const float4*)(lat + (size_t)rowBase * DDIM);
        for (int i = tid; i < ROWS_PER_CTA * (DDIM / 4); i += NTHREADS) {
            int r = i >> 4;               // row within tile
            int v = i & 15;               // float4 index within row
            float4 x = X4[i];
            Xs[(v * 4 + 0) * XS_STRIDE + r] = x.x;
            Xs[(v * 4 + 1) * XS_STRIDE + r] = x.y;
            Xs[(v * 4 + 2) * XS_STRIDE + r] = x.z;
            Xs[(v * 4 + 3) * XS_STRIDE + r] = x.w;
        }
    }
    __syncthreads();

    // ---- ||x||^2 per row: fp32 sequential (square then add, no fusion) ----
    if (tid < ROWS_PER_CTA) {
        float s = 0.f;
        #pragma unroll
        for (int d = 0; d < DDIM; d++) {
            float v = Xs[d * XS_STRIDE + tid];
            s = __fadd_rn(s, __fmul_rn(v, v));
        }
        As[tid] = s;
    }
    __syncthreads();

    float a[8];
    #pragma unroll
    for (int i = 0; i < 8; i++) a[i] = As[ty * 8 + i];

    float bestD[8];
    int   bestI[8];
    #pragma unroll
    for (int i = 0; i < 8; i++) { bestD[i] = CUDART_INF_F; bestI[i] = 0; }

    for (int ch = 0; ch < NCHUNKS; ch++) {
        const int kBase = ch * CANDS_PER_CHUNK;

        // ---- load E chunk (32KB contiguous) transposed ----
        {
            const float4* E4 = (const float4*)(emb + (size_t)kBase * DDIM);
            for (int i = tid; i < CANDS_PER_CHUNK * (DDIM / 4); i += NTHREADS) {
                int c = i >> 4;
                int v = i & 15;
                float4 e = E4[i];
                Es[(v * 4 + 0) * XS_STRIDE + c] = e.x;
                Es[(v * 4 + 1) * XS_STRIDE + c] = e.y;
                Es[(v * 4 + 2) * XS_STRIDE + c] = e.z;
                Es[(v * 4 + 3) * XS_STRIDE + c] = e.w;
            }
        }
        __syncthreads();

        // ---- 8x8 register-tiled dot products, sequential in d (fmaf chain) ----
        float acc[8][8];
        #pragma unroll
        for (int i = 0; i < 8; i++)
            #pragma unroll
            for (int j = 0; j < 8; j++) acc[i][j] = 0.f;

        #pragma unroll 8
        for (int kd = 0; kd < DDIM; kd++) {
            const float* xr = &Xs[kd * XS_STRIDE + ty * 8];
            const float* er = &Es[kd * XS_STRIDE + tx * 8];
            float4 x0 = *(const float4*)(xr);
            float4 x1 = *(const float4*)(xr + 4);
            float4 e0 = *(const float4*)(er);
            float4 e1 = *(const float4*)(er + 4);
            float xv[8] = {x0.x, x0.y, x0.z, x0.w, x1.x, x1.y, x1.z, x1.w};
            float ev[8] = {e0.x, e0.y, e0.z, e0.w, e1.x, e1.y, e1.z, e1.w};
            #pragma unroll
            for (int i = 0; i < 8; i++)
                #pragma unroll
                for (int j = 0; j < 8; j++)
                    acc[i][j] = fmaf(xv[i], ev[j], acc[i][j]);
        }

        // ---- dist = fl(fl(a + b) - 2c); strict < keeps first index ----
        #pragma unroll
        for (int j = 0; j < 8; j++) {
            int k = kBase + tx * 8 + j;
            float bk = g_bs[k];
            #pragma unroll
            for (int i = 0; i < 8; i++) {
                float dist = __fsub_rn(__fadd_rn(a[i], bk), 2.0f * acc[i][j]);
                if (dist < bestD[i]) { bestD[i] = dist; bestI[i] = k; }
            }
        }
        __syncthreads();   // before Es is overwritten
    }

    // ---- cross-thread argmin over the 16 tx-lanes (same rows), first-index tie-break ----
    #pragma unroll
    for (int i = 0; i < 8; i++) {
        float d = bestD[i];
        int   idx = bestI[i];
        #pragma unroll
        for (int off = 8; off >= 1; off >>= 1) {
            float od = __shfl_xor_sync(0xffffffffu, d, off);
            int   oi = __shfl_xor_sync(0xffffffffu, idx, off);
            if (od < d || (od == d && oi < idx)) { d = od; idx = oi; }
        }
        bestI[i] = idx;   // all 16 lanes now agree
    }

    // ---- gather + straight-through output + loss partial ----
    double ls = 0.0;
    #pragma unroll
    for (int i = 0; i < 8; i++) {
        int row = rowBase + ty * 8 + i;
        int idx = bestI[i];
        float4 q = *(const float4*)(emb + (size_t)idx * DDIM + tx * 4);
        float4 l = *(const float4*)(lat + (size_t)row * DDIM + tx * 4);
        float t0 = __fsub_rn(q.x, l.x);
        float t1 = __fsub_rn(q.y, l.y);
        float t2 = __fsub_rn(q.z, l.z);
        float t3 = __fsub_rn(q.w, l.w);
        ls += (double)t0 * (double)t0;
        ls += (double)t1 * (double)t1;
        ls += (double)t2 * (double)t2;
        ls += (double)t3 * (double)t3;
        size_t ob = (size_t)row * DDIM + tx * 4;
        quant[ob + 0] = __fadd_rn(l.x, t0);
        quant[ob + 1] = __fadd_rn(l.y, t1);
        quant[ob + 2] = __fadd_rn(l.z, t2);
        quant[ob + 3] = __fadd_rn(l.w, t3);
    }

    // ---- block reduce of loss partial (deterministic) ----
    #pragma unroll
    for (int off = 16; off >= 1; off >>= 1)
        ls += __shfl_xor_sync(0xffffffffu, ls, off);
    __shared__ double wsum[NTHREADS / 32];
    int warp = tid >> 5;
    if ((tid & 31) == 0) wsum[warp] = ls;
    __syncthreads();
    if (tid == 0) {
        double s = 0.0;
        #pragma unroll
        for (int w = 0; w < NTHREADS / 32; w++) s += wsum[w];
        g_part[blockIdx.x] = s;
    }
}

// ---------------- kernel 2: finalize vq_loss ----------------
__global__ void vq_finalize_kernel(float* __restrict__ out) {
    __shared__ double sm2[NCTAS];
    int t = threadIdx.x;
    sm2[t] = g_part[t];
    __syncthreads();
    for (int s = NCTAS / 2; s >= 1; s >>= 1) {
        if (t < s) sm2[t] += sm2[t + s];
        __syncthreads();
    }
    if (t == 0) {
        double m = sm2[0] / (double)(NROWS * DDIM);
        // vq_loss = embedding_loss + 0.25 * commitment_loss; both equal m numerically
        out[0] = (float)(1.25 * m);
    }
}

extern "C" void kernel_launch(void* const* d_in, const int* in_sizes, int n_in,
                              void* d_out, int out_size) {
    const float* lat = (const float*)d_in[0];   // latents  [65536, 64]
    const float* emb = (const float*)d_in[1];   // embedding [512, 64]
    float* out = (float*)d_out;                 // [1 + 65536*64]

    const size_t smem = (2 * DDIM * XS_STRIDE + ROWS_PER_CTA) * sizeof(float); // 68,096 B
    cudaFuncSetAttribute(vq_main_kernel, cudaFuncAttributeMaxDynamicSharedMemorySize, (int)smem);

    vq_bs_kernel<<<1, KEMB>>>(emb);
    vq_main_kernel<<<NCTAS, NTHREADS, smem>>>(lat, emb, out + 1);
    vq_finalize_kernel<<<1, NCTAS>>>(out);
}

// round 2
// speedup vs baseline: 1.1745x; 1.1745x over previous
#include <cuda_runtime.h>
#include <math_constants.h>
#include <cstdint>

// VectorQuantizer: latents [64,32,32,64] f32, embedding [512,64] f32
// out[0] = vq_loss, out[1..] = quantized_st.
// Numerics contract (verified rel_err==0.0 in R1): dist = fl(fl(a+b) - 2c)
// with a,b,c each built from sequential fp32 mul/add/fma chains in d-order.
// fma.rn.f32x2 performs two independent IEEE fp32 FMAs -> bit-identical.

#define NROWS 65536
#define KEMB 512
#define DDIM 64
#define ROWS_PER_CTA 128
#define CANDS_PER_CHUNK 128
#define NCHUNKS (KEMB / CANDS_PER_CHUNK)   // 4
#define NTHREADS 256
#define NCTAS (NROWS / ROWS_PER_CTA)       // 512
#define XS_STRIDE 132                      // padded row stride (floats)

__device__ double g_part[NCTAS];  // per-CTA loss partial sums

__device__ __forceinline__ unsigned long long pack2(float lo, float hi) {
    unsigned long long r;
    asm("mov.b64 %0, {%1, %2};" : "=l"(r) : "f"(lo), "f"(hi));
    return r;
}
__device__ __forceinline__ void unpack2(unsigned long long v, float& lo, float& hi) {
    asm("mov.b64 {%0, %1}, %2;" : "=f"(lo), "=f"(hi) : "l"(v));
}
__device__ __forceinline__ unsigned long long fma2(unsigned long long a,
                                                   unsigned long long b,
                                                   unsigned long long c) {
    unsigned long long r;
    asm("fma.rn.f32x2 %0, %1, %2, %3;" : "=l"(r) : "l"(a), "l"(b), "l"(c));
    return r;
}

// ---------------- kernel 1: distances + argmin + gather + ST + loss ----------------
__global__ __launch_bounds__(NTHREADS, 2)
void vq_main_kernel(const float* __restrict__ lat,
                    const float* __restrict__ emb,
                    float* __restrict__ quant /* = d_out + 1 */)
{
    extern __shared__ float sm[];
    float* Xs = sm;                       // [DDIM][XS_STRIDE] transposed latents tile
    float* Es = sm + DDIM * XS_STRIDE;    // [DDIM][XS_STRIDE] transposed code chunk
    float* As = Es + DDIM * XS_STRIDE;    // [ROWS_PER_CTA] ||x||^2
    float* Bs = As + ROWS_PER_CTA;        // [CANDS_PER_CHUNK] ||e||^2 (this chunk)

    const int tid = threadIdx.x;
    const int tx = tid & 15;              // candidate group 0..15
    const int ty = tid >> 4;              // row group 0..15
    const int rowBase = blockIdx.x * ROWS_PER_CTA;

    // ---- load X tile (32KB contiguous) transposed into smem ----
    {
        const float4* X4 = (const float4*)(lat + (size_t)rowBase * DDIM);
        for (int i = tid; i < ROWS_PER_CTA * (DDIM / 4); i += NTHREADS) {
            int r = i >> 4;               // row within tile
            int v = i & 15;               // float4 index within row
            float4 x = X4[i];
            Xs[(v * 4 + 0) * XS_STRIDE + r] = x.x;
            Xs[(v * 4 + 1) * XS_STRIDE + r] = x.y;
            Xs[(v * 4 + 2) * XS_STRIDE + r] = x.z;
            Xs[(v * 4 + 3) * XS_STRIDE + r] = x.w;
        }
    }
    __syncthreads();

    // ---- ||x||^2 per row: fp32 sequential (square then add, no fusion) ----
    if (tid < ROWS_PER_CTA) {
        float s = 0.f;
        #pragma unroll
        for (int d = 0; d < DDIM; d++) {
            float v = Xs[d * XS_STRIDE + tid];
            s = __fadd_rn(s, __fmul_rn(v, v));
        }
        As[tid] = s;
    }
    __syncthreads();

    float a[8];
    #pragma unroll
    for (int i = 0; i < 8; i++) a[i] = As[ty * 8 + i];

    float bestD[8];
    int   bestI[8];
    #pragma unroll
    for (int i = 0; i < 8; i++) { bestD[i] = CUDART_INF_F; bestI[i] = 0; }

    for (int ch = 0; ch < NCHUNKS; ch++) {
        const int kBase = ch * CANDS_PER_CHUNK;

        // ---- load E chunk (32KB contiguous) transposed ----
        {
            const float4* E4 = (const float4*)(emb + (size_t)kBase * DDIM);
            for (int i = tid; i < CANDS_PER_CHUNK * (DDIM / 4); i += NTHREADS) {
                int c = i >> 4;
                int v = i & 15;
                float4 e = E4[i];
                Es[(v * 4 + 0) * XS_STRIDE + c] = e.x;
                Es[(v * 4 + 1) * XS_STRIDE + c] = e.y;
                Es[(v * 4 + 2) * XS_STRIDE + c] = e.z;
                Es[(v * 4 + 3) * XS_STRIDE + c] = e.w;
            }
        }
        __syncthreads();

        // ---- ||e||^2 for this chunk: same sequential order as emb rows ----
        if (tid < CANDS_PER_CHUNK) {
            float s = 0.f;
            #pragma unroll
            for (int d = 0; d < DDIM; d++) {
                float v = Es[d * XS_STRIDE + tid];
                s = __fadd_rn(s, __fmul_rn(v, v));
            }
            Bs[tid] = s;
        }

        // ---- 8x8 register tile via packed dual-fp32 FMA (bit-exact fmaf x2) ----
        unsigned long long acc2[8][4];
        #pragma unroll
        for (int i = 0; i < 8; i++)
            #pragma unroll
            for (int jp = 0; jp < 4; jp++) acc2[i][jp] = 0ull;

        #pragma unroll 8
        for (int kd = 0; kd < DDIM; kd++) {
            const float* xr = &Xs[kd * XS_STRIDE + ty * 8];
            const float* er = &Es[kd * XS_STRIDE + tx * 8];
            float4 x0 = *(const float4*)(xr);
            float4 x1 = *(const float4*)(xr + 4);
            unsigned long long xb[8];
            xb[0] = pack2(x0.x, x0.x); xb[1] = pack2(x0.y, x0.y);
            xb[2] = pack2(x0.z, x0.z); xb[3] = pack2(x0.w, x0.w);
            xb[4] = pack2(x1.x, x1.x); xb[5] = pack2(x1.y, x1.y);
            xb[6] = pack2(x1.z, x1.z); xb[7] = pack2(x1.w, x1.w);
            unsigned long long e2[4];
            #pragma unroll
            for (int jp = 0; jp < 4; jp++)
                e2[jp] = *(const unsigned long long*)(er + 2 * jp);
            #pragma unroll
            for (int i = 0; i < 8; i++)
                #pragma unroll
                for (int jp = 0; jp < 4; jp++)
                    acc2[i][jp] = fma2(xb[i], e2[jp], acc2[i][jp]);
        }

        __syncthreads();   // Bs visible; kd-loop done before Es reuse

        // ---- dist = fl(fl(a + b) - 2c); strict < keeps first index ----
        #pragma unroll
        for (int jp = 0; jp < 4; jp++) {
            int k0 = kBase + tx * 8 + 2 * jp;
            float bk0 = Bs[tx * 8 + 2 * jp];
            float bk1 = Bs[tx * 8 + 2 * jp + 1];
            #pragma unroll
            for (int i = 0; i < 8; i++) {
                float c0, c1;
                unpack2(acc2[i][jp], c0, c1);
                float d0 = __fsub_rn(__fadd_rn(a[i], bk0), 2.0f * c0);
                float d1 = __fsub_rn(__fadd_rn(a[i], bk1), 2.0f * c1);
                if (d0 < bestD[i]) { bestD[i] = d0; bestI[i] = k0; }
                if (d1 < bestD[i]) { bestD[i] = d1; bestI[i] = k0 + 1; }
            }
        }
    }

    // ---- cross-thread argmin over the 16 tx-lanes, first-index tie-break ----
    #pragma unroll
    for (int i = 0; i < 8; i++) {
        float d = bestD[i];
        int   idx = bestI[i];
        #pragma unroll
        for (int off = 8; off >= 1; off >>= 1) {
            float od = __shfl_xor_sync(0xffffffffu, d, off);
            int   oi = __shfl_xor_sync(0xffffffffu, idx, off);
            if (od < d || (od == d && oi < idx)) { d = od; idx = oi; }
        }
        bestI[i] = idx;   // all 16 lanes now agree
    }

    // ---- gather + straight-through output + loss partial ----
    double ls = 0.0;
    #pragma unroll
    for (int i = 0; i < 8; i++) {
        int row = rowBase + ty * 8 + i;
        int idx = bestI[i];
        float4 q = *(const float4*)(emb + (size_t)idx * DDIM + tx * 4);
        float4 l = *(const float4*)(lat + (size_t)row * DDIM + tx * 4);
        float t0 = __fsub_rn(q.x, l.x);
        float t1 = __fsub_rn(q.y, l.y);
        float t2 = __fsub_rn(q.z, l.z);
        float t3 = __fsub_rn(q.w, l.w);
        ls += (double)t0 * (double)t0;
        ls += (double)t1 * (double)t1;
        ls += (double)t2 * (double)t2;
        ls += (double)t3 * (double)t3;
        size_t ob = (size_t)row * DDIM + tx * 4;
        quant[ob + 0] = __fadd_rn(l.x, t0);
        quant[ob + 1] = __fadd_rn(l.y, t1);
        quant[ob + 2] = __fadd_rn(l.z, t2);
        quant[ob + 3] = __fadd_rn(l.w, t3);
    }

    // ---- block reduce of loss partial (deterministic) ----
    #pragma unroll
    for (int off = 16; off >= 1; off >>= 1)
        ls += __shfl_xor_sync(0xffffffffu, ls, off);
    __shared__ double wsum[NTHREADS / 32];
    int warp = tid >> 5;
    if ((tid & 31) == 0) wsum[warp] = ls;
    __syncthreads();
    if (tid == 0) {
        double s = 0.0;
        #pragma unroll
        for (int w = 0; w < NTHREADS / 32; w++) s += wsum[w];
        g_part[blockIdx.x] = s;
    }
}

// ---------------- kernel 2: finalize vq_loss ----------------
__global__ void vq_finalize_kernel(float* __restrict__ out) {
    __shared__ double sm2[NCTAS];
    int t = threadIdx.x;
    sm2[t] = g_part[t];
    __syncthreads();
    for (int s = NCTAS / 2; s >= 1; s >>= 1) {
        if (t < s) sm2[t] += sm2[t + s];
        __syncthreads();
    }
    if (t == 0) {
        double m = sm2[0] / (double)(NROWS * DDIM);
        out[0] = (float)(1.25 * m);
    }
}

extern "C" void kernel_launch(void* const* d_in, const int* in_sizes, int n_in,
                              void* d_out, int out_size) {
    const float* lat = (const float*)d_in[0];   // latents  [65536, 64]
    const float* emb = (const float*)d_in[1];   // embedding [512, 64]
    float* out = (float*)d_out;                 // [1 + 65536*64]

    const size_t smem = (2 * DDIM * XS_STRIDE + ROWS_PER_CTA + CANDS_PER_CHUNK)
                        * sizeof(float); // 68,608 B
    cudaFuncSetAttribute(vq_main_kernel, cudaFuncAttributeMaxDynamicSharedMemorySize, (int)smem);

    vq_main_kernel<<<NCTAS, NTHREADS, smem>>>(lat, emb, out + 1);
    vq_finalize_kernel<<<1, NCTAS>>>(out);
}